// round 16
// baseline (speedup 1.0000x reference)
#include <cuda_runtime.h>
#include <cuda_fp16.h>
#include <cstdint>
#include <math.h>

// TISA biased attention, round 16:
//  - fused chunk pipeline: tile body = 4x (QK n-pair -> softmax -> PV k-chunk),
//    exposing cross-chunk ILP (QK of p+1 overlaps softmax/PV of p)
//  - cs live range 32 -> 8 regs; TBL 256 -> smem 43KB -> occ 5 (2.5 warps/SMSP)
//  - xi u16 bitfield decode (ii = xi>>7, fr = (xi&127)/128): no float floor
//  - 1-term fp16 mma.sync, coalesced prepass, xi u16 pre-pass, cp.async x2 buf
// B=2, L=2048, H=8, D=64, S=2, F=5. Output fp32 (B,L,H,D).

namespace {
constexpr int Lc = 2048, Hc = 8, Fc = 5;
constexpr int TQ = 64;
constexpr int TBL = 256;
constexpr int OFF_Q  = 0;          // QH 8192
constexpr int OFF_B0 = 8192;       // buf0: KH 8192 | VH 8192
constexpr int OFF_B1 = 24576;      // buf1
constexpr int OFF_BTB = 40960;     // 256 x float2 = 2KB
constexpr int SMEM_BYTES = 43008;  // x5 CTA = 215KB <= 228KB
constexpr float DMAX = 1.4142136f;
constexpr float IDXSCALE = (float)(TBL - 1) / DMAX;
constexpr float STEP = DMAX / (float)(TBL - 1);
constexpr float L2E = 1.44269504f;
constexpr float SHIFT = 8.0f;
constexpr float INV128 = 0.0078125f;
}

// pre-split fp16 ldmatrix-swizzled tiles (single plane each)
__device__ __align__(16) unsigned char gQ[512][8192];
__device__ __align__(16) unsigned char gK[512][8192];
__device__ __align__(16) unsigned char gV[512][8192];
// xi16[b][q][k] = round(|qs-ks| * IDXSCALE * 128), shared across heads
__device__ __align__(16) unsigned short gXi16[2][2048][2048];

__device__ __forceinline__ uint32_t smem_u32(const void* p) {
    uint32_t a;
    asm("{ .reg .u64 t; cvta.to.shared.u64 t, %1; cvt.u32.u64 %0, t; }"
        : "=r"(a) : "l"(p));
    return a;
}
__device__ __forceinline__ float fast_sqrtf(float x) {
    float r; asm("sqrt.approx.f32 %0, %1;" : "=f"(r) : "f"(x)); return r;
}
__device__ __forceinline__ float ex2f(float x) {
    float r; asm("ex2.approx.ftz.f32 %0, %1;" : "=f"(r) : "f"(x)); return r;
}
__device__ __forceinline__ uint32_t packh2(float lo, float hi) {
    const __half2 h = __floats2half2_rn(lo, hi);
    return *reinterpret_cast<const uint32_t*>(&h);
}

__device__ __forceinline__ void cp16(uint32_t dst, const void* src) {
    asm volatile("cp.async.cg.shared.global [%0], [%1], 16;"
                 :: "r"(dst), "l"(src) : "memory");
}
__device__ __forceinline__ void cp_commit() {
    asm volatile("cp.async.commit_group;" ::: "memory");
}
template <int N>
__device__ __forceinline__ void cp_wait() {
    asm volatile("cp.async.wait_group %0;" :: "n"(N) : "memory");
}

__device__ __forceinline__ void ldmx4(uint32_t& r0, uint32_t& r1,
                                      uint32_t& r2, uint32_t& r3, uint32_t addr) {
    asm volatile("ldmatrix.sync.aligned.m8n8.x4.shared.b16 {%0,%1,%2,%3}, [%4];"
                 : "=r"(r0), "=r"(r1), "=r"(r2), "=r"(r3) : "r"(addr));
}
__device__ __forceinline__ void ldmx4t(uint32_t& r0, uint32_t& r1,
                                       uint32_t& r2, uint32_t& r3, uint32_t addr) {
    asm volatile("ldmatrix.sync.aligned.m8n8.x4.trans.shared.b16 {%0,%1,%2,%3}, [%4];"
                 : "=r"(r0), "=r"(r1), "=r"(r2), "=r"(r3) : "r"(addr));
}
__device__ __forceinline__ void mma16816(float* c, const uint32_t* a,
                                         const uint32_t b0, const uint32_t b1) {
    asm volatile("mma.sync.aligned.m16n8k16.row.col.f32.f16.f16.f32 "
                 "{%0,%1,%2,%3}, {%4,%5,%6,%7}, {%8,%9}, {%0,%1,%2,%3};"
                 : "+f"(c[0]), "+f"(c[1]), "+f"(c[2]), "+f"(c[3])
                 : "r"(a[0]), "r"(a[1]), "r"(a[2]), "r"(a[3]), "r"(b0), "r"(b1));
}

// ---- pre-pass A: fp32 -> swizzled fp16 tiles, coalesced 16B-block items ----
__global__ __launch_bounds__(128)
void tisa_prepass_qkv(const float* __restrict__ gq,
                      const float* __restrict__ gk,
                      const float* __restrict__ gv)
{
    const int t3   = blockIdx.y;           // 0=Q,1=K,2=V
    const int idx  = blockIdx.x;           // (b*8+h)*32 + tile
    const int tile = idx & 31;
    const int bh   = idx >> 5;
    const int h    = bh & 7, b = bh >> 3;
    const int tid  = threadIdx.x;

    const float* src = (t3 == 0) ? gq : (t3 == 1) ? gk : gv;
    const float sc = (t3 == 0) ? 0.125f : 1.0f;
    unsigned char* dst = (t3 == 0) ? &gQ[idx][0]
                       : (t3 == 1) ? &gK[idx][0] : &gV[idx][0];

#pragma unroll
    for (int i = 0; i < 4; i++) {
        const int item = tid + 128 * i;    // 512 items = 64 rows x 8 blocks
        const int crow = item >> 3;
        const int j    = item & 7;
        const float* sp = src +
            ((size_t)(((b * Lc + tile * 64 + crow) * Hc) + h)) * 64 + j * 8;
        float4 v0 = *(const float4*)(sp);
        float4 v1 = *(const float4*)(sp + 4);
        v0.x *= sc; v0.y *= sc; v0.z *= sc; v0.w *= sc;
        v1.x *= sc; v1.y *= sc; v1.z *= sc; v1.w *= sc;
        const uint4 out = make_uint4(packh2(v0.x, v0.y), packh2(v0.z, v0.w),
                                     packh2(v1.x, v1.y), packh2(v1.z, v1.w));
        const int off = crow * 128 + ((j * 16) ^ ((crow & 7) << 4));
        *(uint4*)(dst + off) = out;
    }
}

// ---- pre-pass B: xi u16 fixed-point, 8 consecutive k per thread ----
__global__ __launch_bounds__(256)
void tisa_prepass_xi(const float* __restrict__ gqs,
                     const float* __restrict__ gks)
{
    const int row = blockIdx.x;            // b*2048 + q
    const int b   = row >> 11;
    const float2 qc = *(const float2*)(gqs + (size_t)row * 2);
    const float2* ks2 = (const float2*)(gks + (size_t)b * Lc * 2);
    const int k0 = threadIdx.x * 8;

    uint32_t pk[4];
#pragma unroll
    for (int i = 0; i < 4; i++) {
        const float2 ka = ks2[k0 + 2 * i];
        const float2 kb = ks2[k0 + 2 * i + 1];
        float dx = qc.x - ka.x, dy = qc.y - ka.y;
        const float x0 = fast_sqrtf(fmaf(dx, dx, dy * dy)) * (IDXSCALE * 128.f);
        dx = qc.x - kb.x; dy = qc.y - kb.y;
        const float x1 = fast_sqrtf(fmaf(dx, dx, dy * dy)) * (IDXSCALE * 128.f);
        pk[i] = (__float2uint_rn(x0) & 0xffffu) | (__float2uint_rn(x1) << 16);
    }
    *(uint4*)(&gXi16[b][row & 2047][k0]) = make_uint4(pk[0], pk[1], pk[2], pk[3]);
}

// ------------------------------- main kernel --------------------------------
__global__ __launch_bounds__(128, 5)
void tisa_attn_kernel(const float* __restrict__ ga,
                      const float* __restrict__ gb,
                      const float* __restrict__ gc,
                      float* __restrict__ gout)
{
    extern __shared__ __align__(1024) char smc[];
    const uint32_t sbase = smem_u32(smc);
    const int tid  = threadIdx.x;
    const int w    = tid >> 5;
    const int lane = tid & 31;
    const int g    = lane >> 2;
    const int tig  = lane & 3;
    const int qt   = blockIdx.x;
    const int h    = blockIdx.y;
    const int bb   = blockIdx.z;
    const int bh32 = (bb * Hc + h) * 32;

    const int mrow = lane & 7, msel = lane >> 3;
    const int sx   = mrow << 4;
    const int pa_row = ((msel & 1) << 3) + mrow;
    const int pa_c   = (msel >> 1) << 4;
    const int pb_row = ((msel >> 1) << 3) + mrow;
    const int pb_c   = (msel & 1) << 4;

    // ---- fetch Q plane (8KB), group 0 ----
    {
        const unsigned char* qsrc = &gQ[bh32 + qt][0];
#pragma unroll
        for (int i = 0; i < 4; i++)
            cp16(sbase + OFF_Q + (tid + 128 * i) * 16, qsrc + (tid + 128 * i) * 16);
        cp_commit();
    }

    // ---- bias lerp table: (f(d) - SHIFT) * log2e, 256 entries ----
    {
        float2* btab = (float2*)(smc + OFF_BTB);
        float ah[Fc], nb[Fc], ch[Fc];
#pragma unroll
        for (int f = 0; f < Fc; f++) {
            ah[f] = ga[h * Fc + f];
            nb[f] = -fabsf(gb[h * Fc + f]);
            ch[f] = gc[h * Fc + f];
        }
        for (int i = tid; i < TBL; i += 128) {
            const float x0 = i * STEP, x1 = x0 + STEP;
            float f0 = 0.f, f1 = 0.f;
#pragma unroll
            for (int f = 0; f < Fc; f++) {
                const float t0 = x0 - ch[f], t1 = x1 - ch[f];
                f0 = fmaf(ah[f], __expf(nb[f] * t0 * t0), f0);
                f1 = fmaf(ah[f], __expf(nb[f] * t1 * t1), f1);
            }
            btab[i] = make_float2((f0 - SHIFT) * L2E, (f1 - f0) * L2E);
        }
    }

    const int qrow = qt * TQ + 16 * w + g;
    const unsigned short* xr0 = &gXi16[bb][qrow][0];
    const unsigned short* xr1 = &gXi16[bb][qrow + 8][0];

    const unsigned char* kbase = &gK[bh32][0];
    const unsigned char* vbase = &gV[bh32][0];

#define FETCH_TILE(t, bufoff) do {                                             \
        const unsigned char* kb = kbase + (size_t)(t) * 8192;                  \
        const unsigned char* vb = vbase + (size_t)(t) * 8192;                  \
        _Pragma("unroll")                                                      \
        for (int i = 0; i < 4; i++)                                            \
            cp16(sbase + (bufoff) + (tid + 128 * i) * 16,                      \
                 kb + (tid + 128 * i) * 16);                                   \
        _Pragma("unroll")                                                      \
        for (int i = 0; i < 4; i++)                                            \
            cp16(sbase + (bufoff) + 8192 + (tid + 128 * i) * 16,               \
                 vb + (tid + 128 * i) * 16);                                   \
    } while (0)

    FETCH_TILE(0, OFF_B0);
    cp_commit();
    FETCH_TILE(1, OFF_B1);
    cp_commit();
    // groups in flight: [Q][K0V0][K1V1]

    // ---- hoist Q fragments: 16 persistent regs ----
    uint32_t qh[4][4];
    cp_wait<2>();
    __syncthreads();
#pragma unroll
    for (int j = 0; j < 4; j++) {
        const uint32_t aq = sbase + OFF_Q + (16 * w + pa_row) * 128
                            + ((32 * j + pa_c) ^ sx);
        ldmx4(qh[j][0], qh[j][1], qh[j][2], qh[j][3], aq);
    }

    float accO[8][4];
#pragma unroll
    for (int n = 0; n < 8; n++)
#pragma unroll
        for (int e = 0; e < 4; e++) accO[n][e] = 0.f;
    float lrow0 = 0.f, lrow1 = 0.f;

    const float2* btab = (const float2*)(smc + OFF_BTB);

    for (int kt = 0; kt < 32; kt++) {
        cp_wait<1>();
        __syncthreads();
        const uint32_t bo = (kt & 1) ? (uint32_t)OFF_B1 : (uint32_t)OFF_B0;
        const uint32_t* x0p = (const uint32_t*)(xr0 + kt * 64);
        const uint32_t* x1p = (const uint32_t*)(xr1 + kt * 64);

        // ==== fused chunks: p = n-pair of S = k-chunk of PV ====
#pragma unroll
        for (int p = 0; p < 4; p++) {
            // -- xi loads for this chunk (hoistable across p by scheduler) --
            const uint32_t xa0 = x0p[tig + 4 * (2 * p)];
            const uint32_t xa1 = x0p[tig + 4 * (2 * p + 1)];
            const uint32_t xb0 = x1p[tig + 4 * (2 * p)];
            const uint32_t xb1 = x1p[tig + 4 * (2 * p + 1)];

            // -- QK for n = 2p, 2p+1 --
            float cs0[4] = {0.f, 0.f, 0.f, 0.f};
            float cs1[4] = {0.f, 0.f, 0.f, 0.f};
#pragma unroll
            for (int j = 0; j < 4; j++) {
                uint32_t b0, b1, b2, b3;
                ldmx4(b0, b1, b2, b3,
                      sbase + bo + (16 * p + pb_row) * 128 + ((32 * j + pb_c) ^ sx));
                mma16816(cs0, qh[j], b0, b1);
                mma16816(cs1, qh[j], b2, b3);
            }

            // -- softmax chunk: bias via bitfield decode + shifted exp --
            //    xi u16 = d*IDXSCALE*128 ; ii = xi>>7 , fr = (xi&127)/128
#define BIAS_OF(v, sh) ({                                                     \
                const uint32_t _v = (sh) ? ((v) >> 16) : ((v) & 0xffffu);     \
                const float2 _tb = btab[_v >> 7];                             \
                fmaf((float)(_v & 127u) * INV128, _tb.y, _tb.x); })
            const float p0 = ex2f(fmaf(cs0[0], L2E, BIAS_OF(xa0, 0)));
            const float p1 = ex2f(fmaf(cs0[1], L2E, BIAS_OF(xa0, 1)));
            const float p2 = ex2f(fmaf(cs0[2], L2E, BIAS_OF(xb0, 0)));
            const float p3 = ex2f(fmaf(cs0[3], L2E, BIAS_OF(xb0, 1)));
            const float p4 = ex2f(fmaf(cs1[0], L2E, BIAS_OF(xa1, 0)));
            const float p5 = ex2f(fmaf(cs1[1], L2E, BIAS_OF(xa1, 1)));
            const float p6 = ex2f(fmaf(cs1[2], L2E, BIAS_OF(xb1, 0)));
            const float p7 = ex2f(fmaf(cs1[3], L2E, BIAS_OF(xb1, 1)));
#undef BIAS_OF
            lrow0 += (p0 + p1) + (p4 + p5);
            lrow1 += (p2 + p3) + (p6 + p7);

            uint32_t pha[4];
            pha[0] = packh2(p0, p1);
            pha[1] = packh2(p2, p3);
            pha[2] = packh2(p4, p5);
            pha[3] = packh2(p6, p7);

            // -- PV k-chunk p: O[:, all d] += P[:, 16k of chunk p] @ V --
#pragma unroll
            for (int pp = 0; pp < 4; pp++) {
                uint32_t v0, v1, v2, v3;
                ldmx4t(v0, v1, v2, v3,
                       sbase + bo + 8192 + (16 * p + pa_row) * 128
                       + ((32 * pp + pa_c) ^ sx));
                mma16816(accO[2 * pp],     pha, v0, v1);
                mma16816(accO[2 * pp + 1], pha, v2, v3);
            }
        }

        __syncthreads();
        if (kt < 30) FETCH_TILE(kt + 2, bo);
        cp_commit();
    }
#undef FETCH_TILE

    // ---- epilogue ----
    lrow0 += __shfl_xor_sync(0xffffffffu, lrow0, 1);
    lrow0 += __shfl_xor_sync(0xffffffffu, lrow0, 2);
    lrow1 += __shfl_xor_sync(0xffffffffu, lrow1, 1);
    lrow1 += __shfl_xor_sync(0xffffffffu, lrow1, 2);
    const float inv0 = 1.f / lrow0;
    const float inv1 = 1.f / lrow1;

    float* o0 = gout + ((size_t)((bb * Lc + qrow) * Hc + h)) * 64;
    float* o1 = gout + ((size_t)((bb * Lc + qrow + 8) * Hc + h)) * 64;
#pragma unroll
    for (int n = 0; n < 8; n++) {
        const int dv = 8 * n + 2 * tig;
        *(float2*)(o0 + dv) = make_float2(accO[n][0] * inv0, accO[n][1] * inv0);
        *(float2*)(o1 + dv) = make_float2(accO[n][2] * inv1, accO[n][3] * inv1);
    }
}

extern "C" void kernel_launch(void* const* d_in, const int* in_sizes, int n_in,
                              void* d_out, int out_size)
{
    (void)in_sizes; (void)n_in; (void)out_size;
    const float* qs   = (const float*)d_in[0];
    const float* ks   = (const float*)d_in[1];
    const float* vs   = (const float*)d_in[2];
    const float* qs_s = (const float*)d_in[3];
    const float* ks_s = (const float*)d_in[4];
    const float* a    = (const float*)d_in[5];
    const float* b    = (const float*)d_in[6];
    const float* c    = (const float*)d_in[7];
    float* out = (float*)d_out;

    dim3 pgrid(512, 3);
    tisa_prepass_qkv<<<pgrid, 128>>>(qs, ks, vs);
    tisa_prepass_xi<<<4096, 256>>>(qs_s, ks_s);

    cudaFuncSetAttribute(tisa_attn_kernel,
                         cudaFuncAttributeMaxDynamicSharedMemorySize, SMEM_BYTES);
    dim3 grid(Lc / TQ, Hc, 2);   // 512 CTAs, single wave at occ 5
    tisa_attn_kernel<<<grid, 128, SMEM_BYTES>>>(a, b, c, out);
}